// round 15
// baseline (speedup 1.0000x reference)
#include <cuda_runtime.h>
#include <cuda_fp16.h>
#include <cstdint>

#define T_TOK 16384
#define D_DIM 1024
#define E_NUM 8
#define H_DIM 4096
#define CAP   (T_TOK / E_NUM)   // 2048
#define FIX_MAX 2048
#define GAP_THR 0.005f

// ---------------- scratch (device globals: allocation-free) ----------------
__device__ __half   g_xh[(size_t)T_TOK * D_DIM];            // x fp16            32MB
__device__ uint32_t g_wr1p[(size_t)D_DIM * (D_DIM / 2)];    // wr1^T packed       2MB
__device__ uint32_t g_w1p[(size_t)E_NUM * H_DIM * (D_DIM / 2)]; // w1^T packed   64MB
__device__ uint32_t g_w2p[(size_t)E_NUM * D_DIM * (H_DIM / 2)]; // w2^T packed   64MB
__device__ __half   g_r[(size_t)T_TOK * D_DIM];             // router hidden     32MB
__device__ __half   g_h[(size_t)E_NUM * CAP * H_DIM];       // expert hidden    128MB
__device__ float    g_fixlogit[FIX_MAX * E_NUM];
__device__ int      g_fixlist[FIX_MAX];
__device__ int      g_fixcount;
__device__ int      g_eid[T_TOK];
__device__ float    g_gate[T_TOK];
__device__ int      g_idx[E_NUM * CAP];
__device__ float    g_gateslot[E_NUM * CAP];

// ---------------- helpers ----------------
__device__ __forceinline__ uint32_t pack_h2(float a, float b) {
    __half2 h = __floats2half2_rn(a, b);
    return *(uint32_t*)&h;
}
__device__ __forceinline__ uint32_t smem_u32(const void* p) {
    uint32_t a;
    asm("{ .reg .u64 t; cvta.to.shared.u64 t, %1; cvt.u32.u64 %0, t; }"
        : "=r"(a) : "l"(p));
    return a;
}
__device__ __forceinline__ void cp16(uint32_t dst, const void* src, int sz) {
    asm volatile("cp.async.cg.shared.global [%0], [%1], 16, %2;"
                 :: "r"(dst), "l"(src), "r"(sz) : "memory");
}
__device__ __forceinline__ void cp_commit() {
    asm volatile("cp.async.commit_group;" ::: "memory");
}
template <int N>
__device__ __forceinline__ void cp_wait() {
    asm volatile("cp.async.wait_group %0;" :: "n"(N) : "memory");
}
__device__ __forceinline__ void mma_f16(float* d, const uint32_t* a,
                                        const uint32_t* b) {
    asm volatile(
        "mma.sync.aligned.m16n8k16.row.col.f32.f16.f16.f32 "
        "{%0,%1,%2,%3}, {%4,%5,%6,%7}, {%8,%9}, {%0,%1,%2,%3};"
        : "+f"(d[0]), "+f"(d[1]), "+f"(d[2]), "+f"(d[3])
        : "r"(a[0]), "r"(a[1]), "r"(a[2]), "r"(a[3]),
          "r"(b[0]), "r"(b[1]));
}

// ---------------- fused prep: zero out + init routing state + x->fp16 ----------------
__global__ void prep_kernel(float4* out, int n4, int* idx, float* gs,
                            int* fixlist, int* fixcount, float* fixlogit,
                            const float4* __restrict__ x, uint2* __restrict__ xh) {
    int i = blockIdx.x * blockDim.x + threadIdx.x;
    if (i < n4) {
        out[i] = make_float4(0.f, 0.f, 0.f, 0.f);
        float4 v = x[i];
        uint2 o;
        o.x = pack_h2(v.x, v.y);
        o.y = pack_h2(v.z, v.w);
        xh[i] = o;
    }
    if (i < E_NUM * CAP) { idx[i] = T_TOK; gs[i] = 0.f; }
    if (i < FIX_MAX) fixlist[i] = T_TOK;
    if (i < FIX_MAX * E_NUM) fixlogit[i] = 0.f;
    if (i == 0) *fixcount = 0;
}

// ---------------- B packing+transpose: [E][K][N] fp32 -> [E][N][K/2] half2 words ----
// out[n][kh] = half2(B[2kh][n], B[2kh+1][n]); smem-tiled, coalesced both ways.
__global__ void packbT_kernel(const float* __restrict__ in,
                              uint32_t* __restrict__ out, int Kd, int Nd) {
    __shared__ uint32_t t[32][33];
    const int kh0 = blockIdx.x * 32;   // 32 kh = 64 k rows
    const int n0  = blockIdx.y * 32;
    const float* base = in + (size_t)blockIdx.z * Kd * Nd;
    uint32_t*    ob   = out + (size_t)blockIdx.z * Nd * (Kd / 2);
    const int tx = threadIdx.x, ty = threadIdx.y;
#pragma unroll
    for (int j = ty; j < 32; j += 8) {
        int kh = kh0 + j;
        float a = base[(size_t)(2 * kh)     * Nd + n0 + tx];
        float b = base[(size_t)(2 * kh + 1) * Nd + n0 + tx];
        t[j][tx] = pack_h2(a, b);
    }
    __syncthreads();
#pragma unroll
    for (int j = ty; j < 32; j += 8) {
        ob[(size_t)(n0 + j) * (Kd / 2) + kh0 + tx] = t[tx][j];
    }
}

// ---------------- FP16 tensor-core GEMM: 128x128 tile, 256 thr ----------------
// 2-stage cp.async, BK=64, regs capped 2 CTAs/SM, ldmatrix for BOTH A and B.
// A fp16 row-major [M][K]; B n-major packed [N][K/2] half2-kpair words.
// GATHER:  A row m is A[idx[m]] (idx==T_TOK -> zero row)
// SCATTER: output row m goes to Cout[idx[m]]*gate[m] (fp32); idx==T_TOK skipped
// OUTH:    write output as fp16
template<bool GATHER, bool RELU, bool SCATTER, bool OUTH>
__global__ void __launch_bounds__(256, 2)
h16gemm_kernel(const __half* __restrict__ A, const uint32_t* __restrict__ Bp,
               const float* __restrict__ bias, void* __restrict__ CoutV,
               int N, int K,
               const int* __restrict__ rowidx, const float* __restrict__ gates,
               size_t sA, size_t sB, size_t sBias, size_t sC)
{
    constexpr int BM = 128, BN = 128, BK = 64;
    constexpr int KH = BK / 2;                    // 32 words per row
    constexpr int STRIDE = KH + 4;                // 36 words/row (bank: 4r+k)
    constexpr int TILE_BUF = BM * STRIDE;         // 4608 words (A and B identical)
    constexpr int STAGE_WORDS = 2 * TILE_BUF;     // 9216 words per stage

    extern __shared__ uint32_t dsm[];             // 2 stages
    __shared__ int sRow[BM];

    const int e = blockIdx.z;
    const __half*   Ae = A    + (size_t)e * sA;
    const uint32_t* Be = Bp   + (size_t)e * sB;
    const float*    be = bias + (size_t)e * sBias;
    const int*   idxe = (GATHER || SCATTER) ? rowidx + e * CAP : nullptr;
    const float* gte  = SCATTER ? gates + e * CAP : nullptr;

    const int bm0 = blockIdx.y * BM;
    const int bn0 = blockIdx.x * BN;
    const int tid = threadIdx.x;
    const int warp = tid >> 5;
    const int lane = tid & 31;
    const int wr = warp >> 2;      // 0..1  (64-row slabs)
    const int wc = warp & 3;       // 0..3  (32-col slabs)
    const int lr = lane >> 2;      // 0..7
    const int lc = lane & 3;       // 0..3
    const int lm_row = lane & 15;            // ldmatrix A: row within 16-row tile
    const int lm_col = (lane >> 4) << 2;     // ldmatrix A: word col 0 or 4
    const int bl_row  = ((lane >> 4) << 3) + (lane & 7);  // ldmatrix B: n-row in 16
    const int bl_koff = ((lane >> 3) & 1) * 4;            // ldmatrix B: word col 0/4

    if (tid < BM) {
        sRow[tid] = (GATHER || SCATTER) ? idxe[bm0 + tid] : (bm0 + tid);
    }
    __syncthreads();

    const int KW = K / 2;   // B row width in words

    auto cpfill = [&](int s, int step) {
        const int k0 = step * BK;
        uint32_t* Asb = dsm + s * STAGE_WORDS;
        uint32_t* Bsb = Asb + TILE_BUF;
        // A tile: 128 rows x 32 words -> 4 uint4/thread
#pragma unroll
        for (int l = 0; l < 4; l++) {
            int i2  = tid + l * 256;
            int row = i2 >> 3;                // 0..127
            int kq  = (i2 & 7) * 4;           // 0,4,...,28
            uint32_t dst = smem_u32(&Asb[row * STRIDE + kq]);
            if (GATHER) {
                int src = sRow[row];
                bool ok = src < T_TOK;
                cp16(dst, Ae + (size_t)(ok ? src : 0) * K + k0 + kq * 2, ok ? 16 : 0);
            } else {
                cp16(dst, Ae + (size_t)(bm0 + row) * K + k0 + kq * 2, 16);
            }
        }
        // B tile: 128 n-rows x 32 words -> 4 uint4/thread (same shape as A)
#pragma unroll
        for (int l = 0; l < 4; l++) {
            int i2  = tid + l * 256;
            int row = i2 >> 3;
            int kq  = (i2 & 7) * 4;
            cp16(smem_u32(&Bsb[row * STRIDE + kq]),
                 Be + (size_t)(bn0 + row) * KW + k0 / 2 + kq, 16);
        }
        cp_commit();
    };

    float acc[4][4][4];
#pragma unroll
    for (int mt = 0; mt < 4; mt++)
#pragma unroll
        for (int nt = 0; nt < 4; nt++)
#pragma unroll
            for (int i = 0; i < 4; i++) acc[mt][nt][i] = 0.f;

    const int KS = K / BK;
    cpfill(0, 0);

    for (int step = 0; step < KS; step++) {
        const int s = step & 1;
        if (step + 1 < KS) { cpfill(s ^ 1, step + 1); cp_wait<1>(); }
        else               { cp_wait<0>(); }
        __syncthreads();                      // stage 'step' visible

        const uint32_t* As = dsm + s * STAGE_WORDS;
        const uint32_t* Bs = As + TILE_BUF;

#pragma unroll
        for (int kk = 0; kk < 4; kk++) {      // four k16 steps
            const int kb = kk * 8;
            uint32_t a[4][4], b[4][2];
#pragma unroll
            for (int mt = 0; mt < 4; mt++) {
                int m0 = wr * 64 + mt * 16;
                uint32_t addr = smem_u32(&As[(m0 + lm_row) * STRIDE + kb + lm_col]);
                asm volatile(
                    "ldmatrix.sync.aligned.m8n8.x4.shared.b16 {%0,%1,%2,%3}, [%4];"
                    : "=r"(a[mt][0]), "=r"(a[mt][1]),
                      "=r"(a[mt][2]), "=r"(a[mt][3])
                    : "r"(addr));
            }
#pragma unroll
            for (int np = 0; np < 2; np++) {  // 2 n-tile pairs
                int nb = wc * 32 + np * 16;
                uint32_t addr = smem_u32(&Bs[(nb + bl_row) * STRIDE + kb + bl_koff]);
                asm volatile(
                    "ldmatrix.sync.aligned.m8n8.x4.shared.b16 {%0,%1,%2,%3}, [%4];"
                    : "=r"(b[2 * np][0]), "=r"(b[2 * np][1]),
                      "=r"(b[2 * np + 1][0]), "=r"(b[2 * np + 1][1])
                    : "r"(addr));
            }
#pragma unroll
            for (int mt = 0; mt < 4; mt++)
#pragma unroll
                for (int nt = 0; nt < 4; nt++)
                    mma_f16(acc[mt][nt], a[mt], b[nt]);
        }
        __syncthreads();                      // reads done before buf refilled
    }

    // ---- epilogue ----
#pragma unroll
    for (int nt = 0; nt < 4; nt++) {
        int cb = wc * 32 + nt * 8 + 2 * lc;
        float bv0 = be[bn0 + cb];
        float bv1 = be[bn0 + cb + 1];
#pragma unroll
        for (int mt = 0; mt < 4; mt++) {
#pragma unroll
            for (int h = 0; h < 2; h++) {
                int lm = wr * 64 + mt * 16 + lr + h * 8;
                float v0 = acc[mt][nt][h * 2 + 0] + bv0;
                float v1 = acc[mt][nt][h * 2 + 1] + bv1;
                if (RELU) { v0 = fmaxf(v0, 0.f); v1 = fmaxf(v1, 0.f); }
                if (SCATTER) {
                    int token = sRow[lm];
                    if (token >= T_TOK) continue;
                    float g = gte[bm0 + lm];
                    v0 *= g; v1 *= g;
                    float* dst = (float*)CoutV + (size_t)token * N + bn0 + cb;
                    *(float2*)dst = make_float2(v0, v1);
                } else if (OUTH) {
                    __half* dst = (__half*)CoutV + (size_t)e * sC
                                  + (size_t)(bm0 + lm) * N + bn0 + cb;
                    *(uint32_t*)dst = pack_h2(v0, v1);
                } else {
                    float* dst = (float*)CoutV + (size_t)e * sC
                                 + (size_t)(bm0 + lm) * N + bn0 + cb;
                    *(float2*)dst = make_float2(v0, v1);
                }
            }
        }
    }
}

#define GEMM_SMEM (2 * 2 * (128 * 36) * 4)   // 73728 bytes

// ---------------- router logits (fp16 r) + gate + ambiguity flagging ----------------
__global__ void router_logits_kernel(const __half* __restrict__ r,
                                     const float* __restrict__ wr2,
                                     const float* __restrict__ br2,
                                     int* __restrict__ eid,
                                     float* __restrict__ gate,
                                     int* __restrict__ fixlist,
                                     int* __restrict__ fixcount)
{
    int warp = threadIdx.x >> 5;
    int lane = threadIdx.x & 31;
    int t = blockIdx.x * (blockDim.x >> 5) + warp;
    if (t >= T_TOK) return;

    float acc[E_NUM];
#pragma unroll
    for (int e = 0; e < E_NUM; e++) acc[e] = 0.f;

    const __half2* row = (const __half2*)(r + (size_t)t * D_DIM);
    for (int k2 = lane; k2 < D_DIM / 2; k2 += 32) {
        float2 rv = __half22float2(row[k2]);
        const float* w0 = wr2 + (size_t)(2 * k2) * E_NUM;
        const float* w1 = w0 + E_NUM;
#pragma unroll
        for (int e = 0; e < E_NUM; e++) {
            acc[e] = fmaf(rv.x, w0[e], acc[e]);
            acc[e] = fmaf(rv.y, w1[e], acc[e]);
        }
    }
#pragma unroll
    for (int e = 0; e < E_NUM; e++) {
#pragma unroll
        for (int off = 16; off > 0; off >>= 1)
            acc[e] += __shfl_xor_sync(0xFFFFFFFFu, acc[e], off);
    }
    if (lane == 0) {
        float l[E_NUM];
        float m1 = -1e30f, m2 = -1e30f;
        int best = 0;
#pragma unroll
        for (int e = 0; e < E_NUM; e++) {
            l[e] = acc[e] + br2[e];
            if (l[e] > m1) { m2 = m1; m1 = l[e]; best = e; }
            else if (l[e] > m2) m2 = l[e];
        }
        float s = 0.f;
#pragma unroll
        for (int e = 0; e < E_NUM; e++) s += __expf(l[e] - m1);
        eid[t]  = best;
        gate[t] = 1.f / s;
        if (m1 - m2 < GAP_THR) {
            int slot = atomicAdd(fixcount, 1);
            if (slot < FIX_MAX) fixlist[slot] = t;
        }
    }
}

// ---------------- exact fp32 fixup GEMM (BM=32) -> partial logits ----------------
__global__ void __launch_bounds__(256)
fix_gemm_kernel(const float* __restrict__ A, const float* __restrict__ Bmat,
                const float* __restrict__ bias, const float* __restrict__ wr2,
                const int* __restrict__ list, float* __restrict__ fixlogit,
                int N, int K)
{
    constexpr int BM = 32, BN = 128, BK = 16;
    const int bm0 = blockIdx.y * BM;
    const int bn0 = blockIdx.x * BN;
    const int tid = threadIdx.x;
    const int tx = tid & 31;
    const int ty = tid >> 5;

    if (list[bm0] >= T_TOK) return;   // whole block is padding

    __shared__ float As[BK][BM];
    __shared__ float Bs[BK][BN];
    __shared__ int   sRow[BM];
    if (tid < BM) sRow[tid] = list[bm0 + tid];
    __syncthreads();

    float acc[4][4];
#pragma unroll
    for (int i = 0; i < 4; i++)
#pragma unroll
        for (int j = 0; j < 4; j++) acc[i][j] = 0.f;

    for (int k0 = 0; k0 < K; k0 += BK) {
        if (tid < 128) {
            int row = tid >> 2;
            int c4  = (tid & 3) * 4;
            int src = sRow[row];
            float4 v = (src < T_TOK)
                ? *(const float4*)(A + (size_t)src * K + k0 + c4)
                : make_float4(0.f, 0.f, 0.f, 0.f);
            As[c4 + 0][row] = v.x;
            As[c4 + 1][row] = v.y;
            As[c4 + 2][row] = v.z;
            As[c4 + 3][row] = v.w;
        }
#pragma unroll
        for (int l = 0; l < 2; l++) {
            int i4  = tid + l * 256;
            int row = i4 >> 5;
            int c4  = (i4 & 31) * 4;
            *(float4*)(&Bs[row][c4]) =
                *(const float4*)(Bmat + (size_t)(k0 + row) * N + bn0 + c4);
        }
        __syncthreads();
#pragma unroll
        for (int kk = 0; kk < BK; kk++) {
            float a[4], b[4];
            *(float4*)(a) = *(const float4*)(&As[kk][ty * 4]);
            *(float4*)(b) = *(const float4*)(&Bs[kk][tx * 4]);
#pragma unroll
            for (int i = 0; i < 4; i++)
#pragma unroll
                for (int j = 0; j < 4; j++)
                    acc[i][j] = fmaf(a[i], b[j], acc[i][j]);
        }
        __syncthreads();
    }

    float bv[4];
#pragma unroll
    for (int j = 0; j < 4; j++) bv[j] = bias[bn0 + tx * 4 + j];

    float w2r[4][8];
#pragma unroll
    for (int j = 0; j < 4; j++) {
        const float* wrow = wr2 + (size_t)(bn0 + tx * 4 + j) * E_NUM;
        *(float4*)(&w2r[j][0]) = *(const float4*)(wrow);
        *(float4*)(&w2r[j][4]) = *(const float4*)(wrow + 4);
    }

#pragma unroll
    for (int i = 0; i < 4; i++) {
        int lrow = ty * 4 + i;
        if (sRow[lrow] >= T_TOK) continue;
        int slot = bm0 + lrow;
        float o[4];
#pragma unroll
        for (int j = 0; j < 4; j++) o[j] = fmaxf(acc[i][j] + bv[j], 0.f);
        float pl[E_NUM];
#pragma unroll
        for (int e = 0; e < E_NUM; e++) pl[e] = 0.f;
#pragma unroll
        for (int j = 0; j < 4; j++)
#pragma unroll
            for (int e = 0; e < E_NUM; e++)
                pl[e] = fmaf(o[j], w2r[j][e], pl[e]);
#pragma unroll
        for (int e = 0; e < E_NUM; e++)
            atomicAdd(&fixlogit[slot * E_NUM + e], pl[e]);
    }
}

// ---------------- capacity routing (ballot scan, applies fixups first) ----------------
__global__ void route_scan_kernel(const float* __restrict__ fixlogit,
                                  const int* __restrict__ fixlist,
                                  const float* __restrict__ br2,
                                  int* __restrict__ eid,
                                  float* __restrict__ gate,
                                  int* __restrict__ idx,
                                  float* __restrict__ gateslot)
{
    const int e = blockIdx.x;
    const int tid = threadIdx.x;
    const int lane = tid & 31;
    const int w = tid >> 5;

    for (int s = tid; s < FIX_MAX; s += 256) {
        int t = fixlist[s];
        if (t >= T_TOK) continue;
        float l[E_NUM];
        float m1 = -1e30f;
        int best = 0;
#pragma unroll
        for (int q = 0; q < E_NUM; q++) {
            l[q] = fixlogit[s * E_NUM + q] + br2[q];
            if (l[q] > m1) { m1 = l[q]; best = q; }
        }
        float sum = 0.f;
#pragma unroll
        for (int q = 0; q < E_NUM; q++) sum += __expf(l[q] - m1);
        eid[t]  = best;
        gate[t] = 1.f / sum;
    }
    __syncthreads();

    __shared__ int wsum[8];
    int base = 0;
    for (int start = 0; start < T_TOK; start += 256) {
        int t = start + tid;
        bool m = (eid[t] == e);
        unsigned bal = __ballot_sync(0xFFFFFFFFu, m);
        if (lane == 0) wsum[w] = __popc(bal);
        __syncthreads();
        int prefix = 0, total = 0;
#pragma unroll
        for (int q = 0; q < 8; q++) {
            int v = wsum[q];
            if (q < w) prefix += v;
            total += v;
        }
        if (m) {
            int p = base + prefix + __popc(bal & ((1u << lane) - 1u));
            if (p < CAP) {
                idx[e * CAP + p]      = t;
                gateslot[e * CAP + p] = gate[t];
            }
        }
        base += total;
        __syncthreads();
    }
}

// ---------------- launch ----------------
extern "C" void kernel_launch(void* const* d_in, const int* in_sizes, int n_in,
                              void* d_out, int out_size)
{
    const float* x   = (const float*)d_in[0];
    const float* wr1 = (const float*)d_in[1];
    const float* br1 = (const float*)d_in[2];
    const float* wr2 = (const float*)d_in[3];
    const float* br2 = (const float*)d_in[4];
    const float* w1  = (const float*)d_in[5];
    const float* b1  = (const float*)d_in[6];
    const float* w2  = (const float*)d_in[7];
    const float* b2  = (const float*)d_in[8];
    float* out = (float*)d_out;

    __half *xh_ptr, *h_ptr, *r_ptr;
    uint32_t *wr1p_ptr, *w1p_ptr, *w2p_ptr;
    float *gate_ptr, *gs_ptr, *fixlogit_ptr;
    int *eid_ptr, *idx_ptr, *fixlist_ptr, *fixcount_ptr;
    cudaGetSymbolAddress((void**)&xh_ptr,       g_xh);
    cudaGetSymbolAddress((void**)&wr1p_ptr,     g_wr1p);
    cudaGetSymbolAddress((void**)&w1p_ptr,      g_w1p);
    cudaGetSymbolAddress((void**)&w2p_ptr,      g_w2p);
    cudaGetSymbolAddress((void**)&r_ptr,        g_r);
    cudaGetSymbolAddress((void**)&h_ptr,        g_h);
    cudaGetSymbolAddress((void**)&fixlogit_ptr, g_fixlogit);
    cudaGetSymbolAddress((void**)&fixlist_ptr,  g_fixlist);
    cudaGetSymbolAddress((void**)&fixcount_ptr, g_fixcount);
    cudaGetSymbolAddress((void**)&gate_ptr,     g_gate);
    cudaGetSymbolAddress((void**)&gs_ptr,       g_gateslot);
    cudaGetSymbolAddress((void**)&eid_ptr,      g_eid);
    cudaGetSymbolAddress((void**)&idx_ptr,      g_idx);

    cudaFuncSetAttribute(h16gemm_kernel<false, true, false, true>,
                         cudaFuncAttributeMaxDynamicSharedMemorySize, GEMM_SMEM);
    cudaFuncSetAttribute(h16gemm_kernel<true, true, false, true>,
                         cudaFuncAttributeMaxDynamicSharedMemorySize, GEMM_SMEM);
    cudaFuncSetAttribute(h16gemm_kernel<false, false, true, false>,
                         cudaFuncAttributeMaxDynamicSharedMemorySize, GEMM_SMEM);

    // 1) fused prep: zero out, init routing state, x -> fp16
    {
        int n4 = ((size_t)T_TOK * D_DIM) / 4;
        prep_kernel<<<(n4 + 255) / 256, 256>>>(
            (float4*)out, n4, idx_ptr, gs_ptr, fixlist_ptr, fixcount_ptr,
            fixlogit_ptr, (const float4*)x, (uint2*)xh_ptr);
    }

    // 2) weight pack+transpose: wr1 [D][D]->[D][D/2]w, w1 [E][D][H]->[E][H][D/2]w
    {
        dim3 blk(32, 8);
        packbT_kernel<<<dim3(D_DIM / 64, D_DIM / 32, 1), blk>>>(wr1, wr1p_ptr, D_DIM, D_DIM);
        packbT_kernel<<<dim3(D_DIM / 64, H_DIM / 32, E_NUM), blk>>>(w1, w1p_ptr, D_DIM, H_DIM);
    }

    // 3) r = relu(x @ wr1 + br1)   -- fp16 tensor cores, fp16 out
    {
        dim3 grid(D_DIM / 128, T_TOK / 128, 1);
        h16gemm_kernel<false, true, false, true><<<grid, 256, GEMM_SMEM>>>(
            xh_ptr, wr1p_ptr, br1, r_ptr, D_DIM, D_DIM,
            nullptr, nullptr, 0, 0, 0, (size_t)0);
    }

    // 4) logits -> eid, gate, flag ambiguous tokens
    router_logits_kernel<<<T_TOK / 8, 256>>>(r_ptr, wr2, br2, eid_ptr, gate_ptr,
                                             fixlist_ptr, fixcount_ptr);

    // 5) exact fp32 partial logits for flagged tokens
    {
        dim3 grid(D_DIM / 128, FIX_MAX / 32, 1);
        fix_gemm_kernel<<<grid, 256>>>(x, wr1, br1, wr2, fixlist_ptr,
                                       fixlogit_ptr, D_DIM, D_DIM);
    }

    // 6) apply fixups + routing scan
    route_scan_kernel<<<E_NUM, 256>>>(fixlogit_ptr, fixlist_ptr, br2,
                                      eid_ptr, gate_ptr, idx_ptr, gs_ptr);

    // 7) h[e] = relu(gather(xh, idx[e]) @ w1[e] + b1[e])  -> fp16 hidden
    {
        dim3 grid(H_DIM / 128, CAP / 128, E_NUM);
        h16gemm_kernel<true, true, false, true><<<grid, 256, GEMM_SMEM>>>(
            xh_ptr, w1p_ptr, b1, h_ptr, H_DIM, D_DIM,
            idx_ptr, nullptr,
            0, (size_t)H_DIM * (D_DIM / 2), H_DIM, (size_t)CAP * H_DIM);
    }

    // 7b) pack+transpose w2: [E][H][D] -> [E][D][H/2]w
    {
        dim3 blk(32, 8);
        packbT_kernel<<<dim3(H_DIM / 64, D_DIM / 32, E_NUM), blk>>>(w2, w2p_ptr, H_DIM, D_DIM);
    }

    // 8) out[idx] = gate * (h[e] @ w2[e] + b2[e])
    {
        dim3 grid(D_DIM / 128, CAP / 128, E_NUM);
        h16gemm_kernel<false, false, true, false><<<grid, 256, GEMM_SMEM>>>(
            h_ptr, w2p_ptr, b2, out, D_DIM, H_DIM,
            idx_ptr, gs_ptr,
            (size_t)CAP * H_DIM, (size_t)D_DIM * (H_DIM / 2), D_DIM, 0);
    }
}

// round 16
// speedup vs baseline: 1.0326x; 1.0326x over previous
#include <cuda_runtime.h>
#include <cuda_fp16.h>
#include <cstdint>

#define T_TOK 16384
#define D_DIM 1024
#define E_NUM 8
#define H_DIM 4096
#define CAP   (T_TOK / E_NUM)   // 2048
#define FIX_MAX 2048
#define GAP_THR 0.005f

// ---------------- scratch (device globals: allocation-free) ----------------
__device__ __half   g_xh[(size_t)T_TOK * D_DIM];            // x fp16            32MB
__device__ uint32_t g_wr1p[(size_t)(D_DIM / 2) * D_DIM];    // wr1 packed         2MB
__device__ uint32_t g_w1p[(size_t)E_NUM * (D_DIM / 2) * H_DIM]; // w1 packed     64MB
__device__ uint32_t g_w2p[(size_t)E_NUM * (H_DIM / 2) * D_DIM]; // w2 packed     64MB
__device__ __half   g_r[(size_t)T_TOK * D_DIM];             // router hidden     32MB
__device__ __half   g_h[(size_t)E_NUM * CAP * H_DIM];       // expert hidden    128MB
__device__ float    g_fixlogit[FIX_MAX * E_NUM];
__device__ int      g_fixlist[FIX_MAX];
__device__ int      g_fixcount;
__device__ int      g_eid[T_TOK];
__device__ float    g_gate[T_TOK];
__device__ int      g_idx[E_NUM * CAP];
__device__ float    g_gateslot[E_NUM * CAP];

// ---------------- helpers ----------------
__device__ __forceinline__ uint32_t pack_h2(float a, float b) {
    __half2 h = __floats2half2_rn(a, b);
    return *(uint32_t*)&h;
}
__device__ __forceinline__ uint32_t smem_u32(const void* p) {
    uint32_t a;
    asm("{ .reg .u64 t; cvta.to.shared.u64 t, %1; cvt.u32.u64 %0, t; }"
        : "=r"(a) : "l"(p));
    return a;
}
__device__ __forceinline__ void cp16(uint32_t dst, const void* src, int sz) {
    asm volatile("cp.async.cg.shared.global [%0], [%1], 16, %2;"
                 :: "r"(dst), "l"(src), "r"(sz) : "memory");
}
__device__ __forceinline__ void cp_commit() {
    asm volatile("cp.async.commit_group;" ::: "memory");
}
template <int N>
__device__ __forceinline__ void cp_wait() {
    asm volatile("cp.async.wait_group %0;" :: "n"(N) : "memory");
}
__device__ __forceinline__ void mma_f16(float* d, const uint32_t* a,
                                        const uint32_t* b) {
    asm volatile(
        "mma.sync.aligned.m16n8k16.row.col.f32.f16.f16.f32 "
        "{%0,%1,%2,%3}, {%4,%5,%6,%7}, {%8,%9}, {%0,%1,%2,%3};"
        : "+f"(d[0]), "+f"(d[1]), "+f"(d[2]), "+f"(d[3])
        : "r"(a[0]), "r"(a[1]), "r"(a[2]), "r"(a[3]),
          "r"(b[0]), "r"(b[1]));
}

// ---------------- fused prep: zero out + init routing state + x->fp16 ----------------
__global__ void prep_kernel(float4* out, int n4, int* idx, float* gs,
                            int* fixlist, int* fixcount, float* fixlogit,
                            const float4* __restrict__ x, uint2* __restrict__ xh) {
    int i = blockIdx.x * blockDim.x + threadIdx.x;
    if (i < n4) {
        out[i] = make_float4(0.f, 0.f, 0.f, 0.f);
        float4 v = x[i];
        uint2 o;
        o.x = pack_h2(v.x, v.y);
        o.y = pack_h2(v.z, v.w);
        xh[i] = o;
    }
    if (i < E_NUM * CAP) { idx[i] = T_TOK; gs[i] = 0.f; }
    if (i < FIX_MAX) fixlist[i] = T_TOK;
    if (i < FIX_MAX * E_NUM) fixlogit[i] = 0.f;
    if (i == 0) *fixcount = 0;
}

// ---------------- B operand packing: [E][K][N] fp32 -> [E][K/2][N] half2 words ----
__global__ void packb_kernel(const float* __restrict__ in,
                             uint32_t* __restrict__ out, int Kd, int Nd) {
    int i = blockIdx.x * blockDim.x + threadIdx.x;
    int n4 = (Kd / 2) * (Nd / 4);
    if (i >= n4) return;
    int kh = i / (Nd / 4);
    int c4 = (i % (Nd / 4)) * 4;
    const float* base = in + (size_t)blockIdx.y * Kd * Nd;
    float4 r0 = *(const float4*)(base + (size_t)(2 * kh) * Nd + c4);
    float4 r1 = *(const float4*)(base + (size_t)(2 * kh + 1) * Nd + c4);
    uint4 t;
    t.x = pack_h2(r0.x, r1.x);
    t.y = pack_h2(r0.y, r1.y);
    t.z = pack_h2(r0.z, r1.z);
    t.w = pack_h2(r0.w, r1.w);
    *(uint4*)(out + (size_t)blockIdx.y * (Kd / 2) * Nd + (size_t)kh * Nd + c4) = t;
}

// ---------------- FP16 tensor-core GEMM: 128x128 tile, 256 thr ----------------
// 3-stage cp.async ring, ONE barrier per K-step, BK=64, 2 CTAs/SM (regs capped).
// C[M,N] = op(A[M,K] @ B[K,N] + bias[N]); A fp16 row-major, B pre-packed k-pairs.
// GATHER:  A row m is A[idx[m]] (idx==T_TOK -> zero row)
// SCATTER: output row m goes to Cout[idx[m]]*gate[m] (fp32); idx==T_TOK skipped
// OUTH:    write output as fp16
template<bool GATHER, bool RELU, bool SCATTER, bool OUTH>
__global__ void __launch_bounds__(256, 2)
h16gemm_kernel(const __half* __restrict__ A, const uint32_t* __restrict__ Bp,
               const float* __restrict__ bias, void* __restrict__ CoutV,
               int N, int K,
               const int* __restrict__ rowidx, const float* __restrict__ gates,
               size_t sA, size_t sB, size_t sBias, size_t sC)
{
    constexpr int BM = 128, BN = 128, BK = 64;
    constexpr int KH = BK / 2;                    // 32 k-pairs (words per A row)
    constexpr int AS_STRIDE = KH + 4;             // 36 words/row (bank: 4m+k)
    constexpr int BS_STRIDE = BN + 8;             // 136 words/row (bank: 8k+n)
    constexpr int AS_BUF = BM * AS_STRIDE;        // 4608 words
    constexpr int BS_BUF = KH * BS_STRIDE;        // 4352 words
    constexpr int STAGE_WORDS = AS_BUF + BS_BUF;  // 8960 words per stage

    extern __shared__ uint32_t dsm[];             // 3 stages
    __shared__ int sRow[BM];

    const int e = blockIdx.z;
    const __half*   Ae = A    + (size_t)e * sA;
    const uint32_t* Be = Bp   + (size_t)e * sB;
    const float*    be = bias + (size_t)e * sBias;
    const int*   idxe = (GATHER || SCATTER) ? rowidx + e * CAP : nullptr;
    const float* gte  = SCATTER ? gates + e * CAP : nullptr;

    const int bm0 = blockIdx.y * BM;
    const int bn0 = blockIdx.x * BN;
    const int tid = threadIdx.x;
    const int warp = tid >> 5;
    const int lane = tid & 31;
    const int wr = warp >> 2;      // 0..1  (64-row slabs)
    const int wc = warp & 3;       // 0..3  (32-col slabs)
    const int lr = lane >> 2;      // 0..7
    const int lc = lane & 3;       // 0..3
    const int lm_row = lane & 15;            // ldmatrix row within 16-row tile
    const int lm_col = (lane >> 4) << 2;     // ldmatrix word col: 0 or 4

    if (tid < BM) {
        sRow[tid] = (GATHER || SCATTER) ? idxe[bm0 + tid] : (bm0 + tid);
    }
    __syncthreads();

    auto cpfill = [&](int s, int step) {
        const int k0 = step * BK;
        uint32_t* Asb = dsm + s * STAGE_WORDS;
        uint32_t* Bsb = Asb + AS_BUF;
        // A tile: 128 rows x 32 words = 1024 uint4 -> 4 per thread
#pragma unroll
        for (int l = 0; l < 4; l++) {
            int i2  = tid + l * 256;
            int row = i2 >> 3;                // 0..127
            int kq  = (i2 & 7) * 4;           // 0,4,...,28
            uint32_t dst = smem_u32(&Asb[row * AS_STRIDE + kq]);
            if (GATHER) {
                int src = sRow[row];
                bool ok = src < T_TOK;
                cp16(dst, Ae + (size_t)(ok ? src : 0) * K + k0 + kq * 2, ok ? 16 : 0);
            } else {
                cp16(dst, Ae + (size_t)(bm0 + row) * K + k0 + kq * 2, 16);
            }
        }
        // B tile: 32 kh x 128 words = 1024 uint4 -> 4 per thread
#pragma unroll
        for (int l = 0; l < 4; l++) {
            int i2 = tid + l * 256;
            int kh = i2 >> 5;                 // 0..31
            int c4 = (i2 & 31) * 4;           // 0..124
            cp16(smem_u32(&Bsb[kh * BS_STRIDE + c4]),
                 Be + (size_t)(k0 / 2 + kh) * N + bn0 + c4, 16);
        }
        cp_commit();
    };

    float acc[4][4][4];
#pragma unroll
    for (int mt = 0; mt < 4; mt++)
#pragma unroll
        for (int nt = 0; nt < 4; nt++)
#pragma unroll
            for (int i = 0; i < 4; i++) acc[mt][nt][i] = 0.f;

    const int KS = K / BK;
    cpfill(0, 0);
    if (KS > 1) cpfill(1, 1);

    int s = 0;        // stage being consumed
    int f = 2;        // next stage to fill
    for (int step = 0; step < KS; step++) {
        cp_wait<1>();                         // stage 'step' landed
        __syncthreads();                      // + all reads of stage consumed at step-1 done

        if (step + 2 < KS) cpfill(f, step + 2);

        const uint32_t* As = dsm + s * STAGE_WORDS;
        const uint32_t* Bs = As + AS_BUF;

#pragma unroll
        for (int kk = 0; kk < 4; kk++) {      // four k16 steps
            const int kb = kk * 8;
            uint32_t a[4][4], b[4][2];
#pragma unroll
            for (int mt = 0; mt < 4; mt++) {
                int m0 = wr * 64 + mt * 16;
                uint32_t addr = smem_u32(&As[(m0 + lm_row) * AS_STRIDE + kb + lm_col]);
                asm volatile(
                    "ldmatrix.sync.aligned.m8n8.x4.shared.b16 {%0,%1,%2,%3}, [%4];"
                    : "=r"(a[mt][0]), "=r"(a[mt][1]),
                      "=r"(a[mt][2]), "=r"(a[mt][3])
                    : "r"(addr));
            }
#pragma unroll
            for (int nt = 0; nt < 4; nt++) {
                int n0 = wc * 32 + nt * 8;
                b[nt][0] = Bs[(kb + lc    ) * BS_STRIDE + n0 + lr];
                b[nt][1] = Bs[(kb + lc + 4) * BS_STRIDE + n0 + lr];
            }
#pragma unroll
            for (int mt = 0; mt < 4; mt++)
#pragma unroll
                for (int nt = 0; nt < 4; nt++)
                    mma_f16(acc[mt][nt], a[mt], b[nt]);
        }
        s = (s == 2) ? 0 : s + 1;
        f = (f == 2) ? 0 : f + 1;
    }

    // ---- epilogue ----
#pragma unroll
    for (int nt = 0; nt < 4; nt++) {
        int cb = wc * 32 + nt * 8 + 2 * lc;
        float bv0 = be[bn0 + cb];
        float bv1 = be[bn0 + cb + 1];
#pragma unroll
        for (int mt = 0; mt < 4; mt++) {
#pragma unroll
            for (int h = 0; h < 2; h++) {
                int lm = wr * 64 + mt * 16 + lr + h * 8;
                float v0 = acc[mt][nt][h * 2 + 0] + bv0;
                float v1 = acc[mt][nt][h * 2 + 1] + bv1;
                if (RELU) { v0 = fmaxf(v0, 0.f); v1 = fmaxf(v1, 0.f); }
                if (SCATTER) {
                    int token = sRow[lm];
                    if (token >= T_TOK) continue;
                    float g = gte[bm0 + lm];
                    v0 *= g; v1 *= g;
                    float* dst = (float*)CoutV + (size_t)token * N + bn0 + cb;
                    *(float2*)dst = make_float2(v0, v1);
                } else if (OUTH) {
                    __half* dst = (__half*)CoutV + (size_t)e * sC
                                  + (size_t)(bm0 + lm) * N + bn0 + cb;
                    *(uint32_t*)dst = pack_h2(v0, v1);
                } else {
                    float* dst = (float*)CoutV + (size_t)e * sC
                                 + (size_t)(bm0 + lm) * N + bn0 + cb;
                    *(float2*)dst = make_float2(v0, v1);
                }
            }
        }
    }
}

#define GEMM_SMEM (3 * (128 * 36 + 32 * 136) * 4)   // 107520 bytes

// ---------------- router logits (fp16 r) + gate + ambiguity flagging ----------------
__global__ void router_logits_kernel(const __half* __restrict__ r,
                                     const float* __restrict__ wr2,
                                     const float* __restrict__ br2,
                                     int* __restrict__ eid,
                                     float* __restrict__ gate,
                                     int* __restrict__ fixlist,
                                     int* __restrict__ fixcount)
{
    int warp = threadIdx.x >> 5;
    int lane = threadIdx.x & 31;
    int t = blockIdx.x * (blockDim.x >> 5) + warp;
    if (t >= T_TOK) return;

    float acc[E_NUM];
#pragma unroll
    for (int e = 0; e < E_NUM; e++) acc[e] = 0.f;

    const __half2* row = (const __half2*)(r + (size_t)t * D_DIM);
    for (int k2 = lane; k2 < D_DIM / 2; k2 += 32) {
        float2 rv = __half22float2(row[k2]);
        const float* w0 = wr2 + (size_t)(2 * k2) * E_NUM;
        const float* w1 = w0 + E_NUM;
#pragma unroll
        for (int e = 0; e < E_NUM; e++) {
            acc[e] = fmaf(rv.x, w0[e], acc[e]);
            acc[e] = fmaf(rv.y, w1[e], acc[e]);
        }
    }
#pragma unroll
    for (int e = 0; e < E_NUM; e++) {
#pragma unroll
        for (int off = 16; off > 0; off >>= 1)
            acc[e] += __shfl_xor_sync(0xFFFFFFFFu, acc[e], off);
    }
    if (lane == 0) {
        float l[E_NUM];
        float m1 = -1e30f, m2 = -1e30f;
        int best = 0;
#pragma unroll
        for (int e = 0; e < E_NUM; e++) {
            l[e] = acc[e] + br2[e];
            if (l[e] > m1) { m2 = m1; m1 = l[e]; best = e; }
            else if (l[e] > m2) m2 = l[e];
        }
        float s = 0.f;
#pragma unroll
        for (int e = 0; e < E_NUM; e++) s += __expf(l[e] - m1);
        eid[t]  = best;
        gate[t] = 1.f / s;
        if (m1 - m2 < GAP_THR) {
            int slot = atomicAdd(fixcount, 1);
            if (slot < FIX_MAX) fixlist[slot] = t;
        }
    }
}

// ---------------- exact fp32 fixup GEMM (BM=32) -> partial logits ----------------
__global__ void __launch_bounds__(256)
fix_gemm_kernel(const float* __restrict__ A, const float* __restrict__ Bmat,
                const float* __restrict__ bias, const float* __restrict__ wr2,
                const int* __restrict__ list, float* __restrict__ fixlogit,
                int N, int K)
{
    constexpr int BM = 32, BN = 128, BK = 16;
    const int bm0 = blockIdx.y * BM;
    const int bn0 = blockIdx.x * BN;
    const int tid = threadIdx.x;
    const int tx = tid & 31;
    const int ty = tid >> 5;

    if (list[bm0] >= T_TOK) return;   // whole block is padding

    __shared__ float As[BK][BM];
    __shared__ float Bs[BK][BN];
    __shared__ int   sRow[BM];
    if (tid < BM) sRow[tid] = list[bm0 + tid];
    __syncthreads();

    float acc[4][4];
#pragma unroll
    for (int i = 0; i < 4; i++)
#pragma unroll
        for (int j = 0; j < 4; j++) acc[i][j] = 0.f;

    for (int k0 = 0; k0 < K; k0 += BK) {
        if (tid < 128) {
            int row = tid >> 2;
            int c4  = (tid & 3) * 4;
            int src = sRow[row];
            float4 v = (src < T_TOK)
                ? *(const float4*)(A + (size_t)src * K + k0 + c4)
                : make_float4(0.f, 0.f, 0.f, 0.f);
            As[c4 + 0][row] = v.x;
            As[c4 + 1][row] = v.y;
            As[c4 + 2][row] = v.z;
            As[c4 + 3][row] = v.w;
        }
#pragma unroll
        for (int l = 0; l < 2; l++) {
            int i4  = tid + l * 256;
            int row = i4 >> 5;
            int c4  = (i4 & 31) * 4;
            *(float4*)(&Bs[row][c4]) =
                *(const float4*)(Bmat + (size_t)(k0 + row) * N + bn0 + c4);
        }
        __syncthreads();
#pragma unroll
        for (int kk = 0; kk < BK; kk++) {
            float a[4], b[4];
            *(float4*)(a) = *(const float4*)(&As[kk][ty * 4]);
            *(float4*)(b) = *(const float4*)(&Bs[kk][tx * 4]);
#pragma unroll
            for (int i = 0; i < 4; i++)
#pragma unroll
                for (int j = 0; j < 4; j++)
                    acc[i][j] = fmaf(a[i], b[j], acc[i][j]);
        }
        __syncthreads();
    }

    float bv[4];
#pragma unroll
    for (int j = 0; j < 4; j++) bv[j] = bias[bn0 + tx * 4 + j];

    float w2r[4][8];
#pragma unroll
    for (int j = 0; j < 4; j++) {
        const float* wrow = wr2 + (size_t)(bn0 + tx * 4 + j) * E_NUM;
        *(float4*)(&w2r[j][0]) = *(const float4*)(wrow);
        *(float4*)(&w2r[j][4]) = *(const float4*)(wrow + 4);
    }

#pragma unroll
    for (int i = 0; i < 4; i++) {
        int lrow = ty * 4 + i;
        if (sRow[lrow] >= T_TOK) continue;
        int slot = bm0 + lrow;
        float o[4];
#pragma unroll
        for (int j = 0; j < 4; j++) o[j] = fmaxf(acc[i][j] + bv[j], 0.f);
        float pl[E_NUM];
#pragma unroll
        for (int e = 0; e < E_NUM; e++) pl[e] = 0.f;
#pragma unroll
        for (int j = 0; j < 4; j++)
#pragma unroll
            for (int e = 0; e < E_NUM; e++)
                pl[e] = fmaf(o[j], w2r[j][e], pl[e]);
#pragma unroll
        for (int e = 0; e < E_NUM; e++)
            atomicAdd(&fixlogit[slot * E_NUM + e], pl[e]);
    }
}

// ---------------- capacity routing (ballot scan, applies fixups first) ----------------
__global__ void route_scan_kernel(const float* __restrict__ fixlogit,
                                  const int* __restrict__ fixlist,
                                  const float* __restrict__ br2,
                                  int* __restrict__ eid,
                                  float* __restrict__ gate,
                                  int* __restrict__ idx,
                                  float* __restrict__ gateslot)
{
    const int e = blockIdx.x;
    const int tid = threadIdx.x;
    const int lane = tid & 31;
    const int w = tid >> 5;

    for (int s = tid; s < FIX_MAX; s += 256) {
        int t = fixlist[s];
        if (t >= T_TOK) continue;
        float l[E_NUM];
        float m1 = -1e30f;
        int best = 0;
#pragma unroll
        for (int q = 0; q < E_NUM; q++) {
            l[q] = fixlogit[s * E_NUM + q] + br2[q];
            if (l[q] > m1) { m1 = l[q]; best = q; }
        }
        float sum = 0.f;
#pragma unroll
        for (int q = 0; q < E_NUM; q++) sum += __expf(l[q] - m1);
        eid[t]  = best;
        gate[t] = 1.f / sum;
    }
    __syncthreads();

    __shared__ int wsum[8];
    int base = 0;
    for (int start = 0; start < T_TOK; start += 256) {
        int t = start + tid;
        bool m = (eid[t] == e);
        unsigned bal = __ballot_sync(0xFFFFFFFFu, m);
        if (lane == 0) wsum[w] = __popc(bal);
        __syncthreads();
        int prefix = 0, total = 0;
#pragma unroll
        for (int q = 0; q < 8; q++) {
            int v = wsum[q];
            if (q < w) prefix += v;
            total += v;
        }
        if (m) {
            int p = base + prefix + __popc(bal & ((1u << lane) - 1u));
            if (p < CAP) {
                idx[e * CAP + p]      = t;
                gateslot[e * CAP + p] = gate[t];
            }
        }
        base += total;
        __syncthreads();
    }
}

// ---------------- launch ----------------
extern "C" void kernel_launch(void* const* d_in, const int* in_sizes, int n_in,
                              void* d_out, int out_size)
{
    const float* x   = (const float*)d_in[0];
    const float* wr1 = (const float*)d_in[1];
    const float* br1 = (const float*)d_in[2];
    const float* wr2 = (const float*)d_in[3];
    const float* br2 = (const float*)d_in[4];
    const float* w1  = (const float*)d_in[5];
    const float* b1  = (const float*)d_in[6];
    const float* w2  = (const float*)d_in[7];
    const float* b2  = (const float*)d_in[8];
    float* out = (float*)d_out;

    __half *xh_ptr, *h_ptr, *r_ptr;
    uint32_t *wr1p_ptr, *w1p_ptr, *w2p_ptr;
    float *gate_ptr, *gs_ptr, *fixlogit_ptr;
    int *eid_ptr, *idx_ptr, *fixlist_ptr, *fixcount_ptr;
    cudaGetSymbolAddress((void**)&xh_ptr,       g_xh);
    cudaGetSymbolAddress((void**)&wr1p_ptr,     g_wr1p);
    cudaGetSymbolAddress((void**)&w1p_ptr,      g_w1p);
    cudaGetSymbolAddress((void**)&w2p_ptr,      g_w2p);
    cudaGetSymbolAddress((void**)&r_ptr,        g_r);
    cudaGetSymbolAddress((void**)&h_ptr,        g_h);
    cudaGetSymbolAddress((void**)&fixlogit_ptr, g_fixlogit);
    cudaGetSymbolAddress((void**)&fixlist_ptr,  g_fixlist);
    cudaGetSymbolAddress((void**)&fixcount_ptr, g_fixcount);
    cudaGetSymbolAddress((void**)&gate_ptr,     g_gate);
    cudaGetSymbolAddress((void**)&gs_ptr,       g_gateslot);
    cudaGetSymbolAddress((void**)&eid_ptr,      g_eid);
    cudaGetSymbolAddress((void**)&idx_ptr,      g_idx);

    cudaFuncSetAttribute(h16gemm_kernel<false, true, false, true>,
                         cudaFuncAttributeMaxDynamicSharedMemorySize, GEMM_SMEM);
    cudaFuncSetAttribute(h16gemm_kernel<true, true, false, true>,
                         cudaFuncAttributeMaxDynamicSharedMemorySize, GEMM_SMEM);
    cudaFuncSetAttribute(h16gemm_kernel<false, false, true, false>,
                         cudaFuncAttributeMaxDynamicSharedMemorySize, GEMM_SMEM);

    // 1) fused prep: zero out, init routing state, x -> fp16
    {
        int n4 = ((size_t)T_TOK * D_DIM) / 4;
        prep_kernel<<<(n4 + 255) / 256, 256>>>(
            (float4*)out, n4, idx_ptr, gs_ptr, fixlist_ptr, fixcount_ptr,
            fixlogit_ptr, (const float4*)x, (uint2*)xh_ptr);
    }

    // 2) weight packing: wr1, w1
    {
        int nb = (D_DIM / 2) * (D_DIM / 4);
        packb_kernel<<<dim3((nb + 255) / 256, 1), 256>>>(wr1, wr1p_ptr, D_DIM, D_DIM);
        nb = (D_DIM / 2) * (H_DIM / 4);
        packb_kernel<<<dim3((nb + 255) / 256, E_NUM), 256>>>(w1, w1p_ptr, D_DIM, H_DIM);
    }

    // 3) r = relu(x @ wr1 + br1)   -- fp16 tensor cores, fp16 out
    {
        dim3 grid(D_DIM / 128, T_TOK / 128, 1);
        h16gemm_kernel<false, true, false, true><<<grid, 256, GEMM_SMEM>>>(
            xh_ptr, wr1p_ptr, br1, r_ptr, D_DIM, D_DIM,
            nullptr, nullptr, 0, 0, 0, (size_t)0);
    }

    // 4) logits -> eid, gate, flag ambiguous tokens
    router_logits_kernel<<<T_TOK / 8, 256>>>(r_ptr, wr2, br2, eid_ptr, gate_ptr,
                                             fixlist_ptr, fixcount_ptr);

    // 5) exact fp32 partial logits for flagged tokens
    {
        dim3 grid(D_DIM / 128, FIX_MAX / 32, 1);
        fix_gemm_kernel<<<grid, 256>>>(x, wr1, br1, wr2, fixlist_ptr,
                                       fixlogit_ptr, D_DIM, D_DIM);
    }

    // 6) apply fixups + routing scan
    route_scan_kernel<<<E_NUM, 256>>>(fixlogit_ptr, fixlist_ptr, br2,
                                      eid_ptr, gate_ptr, idx_ptr, gs_ptr);

    // 7) h[e] = relu(gather(xh, idx[e]) @ w1[e] + b1[e])  -> fp16 hidden
    {
        dim3 grid(H_DIM / 128, CAP / 128, E_NUM);
        h16gemm_kernel<true, true, false, true><<<grid, 256, GEMM_SMEM>>>(
            xh_ptr, w1p_ptr, b1, h_ptr, H_DIM, D_DIM,
            idx_ptr, nullptr,
            0, (size_t)(D_DIM / 2) * H_DIM, H_DIM, (size_t)CAP * H_DIM);
    }

    // 7b) pack w2
    {
        int nb = (H_DIM / 2) * (D_DIM / 4);
        packb_kernel<<<dim3((nb + 255) / 256, E_NUM), 256>>>(w2, w2p_ptr, H_DIM, D_DIM);
    }

    // 8) out[idx] = gate * (h[e] @ w2[e] + b2[e])
    {
        dim3 grid(D_DIM / 128, CAP / 128, E_NUM);
        h16gemm_kernel<false, false, true, false><<<grid, 256, GEMM_SMEM>>>(
            h_ptr, w2p_ptr, b2, out, D_DIM, H_DIM,
            idx_ptr, gs_ptr,
            (size_t)CAP * H_DIM, (size_t)(H_DIM / 2) * D_DIM, D_DIM, 0);
    }
}

// round 17
// speedup vs baseline: 1.0475x; 1.0144x over previous
#include <cuda_runtime.h>
#include <cuda_fp16.h>
#include <cstdint>

#define T_TOK 16384
#define D_DIM 1024
#define E_NUM 8
#define H_DIM 4096
#define CAP   (T_TOK / E_NUM)   // 2048
#define FIX_MAX 2048
#define GAP_THR 0.005f

// ---------------- scratch (device globals: allocation-free) ----------------
__device__ __half   g_xh[(size_t)T_TOK * D_DIM];            // x fp16            32MB
__device__ uint32_t g_wr1p[(size_t)(D_DIM / 2) * D_DIM];    // wr1 packed         2MB
__device__ uint32_t g_w1p[(size_t)E_NUM * (D_DIM / 2) * H_DIM]; // w1 packed     64MB
__device__ uint32_t g_w2p[(size_t)E_NUM * (H_DIM / 2) * D_DIM]; // w2 packed     64MB
__device__ __half   g_r[(size_t)T_TOK * D_DIM];             // router hidden     32MB
__device__ __half   g_h[(size_t)E_NUM * CAP * H_DIM];       // expert hidden    128MB
__device__ float    g_fixlogit[FIX_MAX * E_NUM];
__device__ int      g_fixlist[FIX_MAX];
__device__ int      g_fixcount;
__device__ int      g_eid[T_TOK];
__device__ float    g_gate[T_TOK];
__device__ int      g_idx[E_NUM * CAP];
__device__ float    g_gateslot[E_NUM * CAP];

// ---------------- helpers ----------------
__device__ __forceinline__ uint32_t pack_h2(float a, float b) {
    __half2 h = __floats2half2_rn(a, b);
    return *(uint32_t*)&h;
}
__device__ __forceinline__ uint32_t smem_u32(const void* p) {
    uint32_t a;
    asm("{ .reg .u64 t; cvta.to.shared.u64 t, %1; cvt.u32.u64 %0, t; }"
        : "=r"(a) : "l"(p));
    return a;
}
__device__ __forceinline__ void cp16(uint32_t dst, const void* src, int sz) {
    asm volatile("cp.async.cg.shared.global [%0], [%1], 16, %2;"
                 :: "r"(dst), "l"(src), "r"(sz) : "memory");
}
__device__ __forceinline__ void cp_commit() {
    asm volatile("cp.async.commit_group;" ::: "memory");
}
template <int N>
__device__ __forceinline__ void cp_wait() {
    asm volatile("cp.async.wait_group %0;" :: "n"(N) : "memory");
}
__device__ __forceinline__ void mma_f16(float* d, const uint32_t* a,
                                        uint32_t b0, uint32_t b1) {
    asm volatile(
        "mma.sync.aligned.m16n8k16.row.col.f32.f16.f16.f32 "
        "{%0,%1,%2,%3}, {%4,%5,%6,%7}, {%8,%9}, {%0,%1,%2,%3};"
        : "+f"(d[0]), "+f"(d[1]), "+f"(d[2]), "+f"(d[3])
        : "r"(a[0]), "r"(a[1]), "r"(a[2]), "r"(a[3]),
          "r"(b0), "r"(b1));
}

// ---------------- fused prep: zero out + init routing state + x->fp16 ----------------
__global__ void prep_kernel(float4* out, int n4, int* idx, float* gs,
                            int* fixlist, int* fixcount, float* fixlogit,
                            const float4* __restrict__ x, uint2* __restrict__ xh) {
    int i = blockIdx.x * blockDim.x + threadIdx.x;
    if (i < n4) {
        out[i] = make_float4(0.f, 0.f, 0.f, 0.f);
        float4 v = x[i];
        uint2 o;
        o.x = pack_h2(v.x, v.y);
        o.y = pack_h2(v.z, v.w);
        xh[i] = o;
    }
    if (i < E_NUM * CAP) { idx[i] = T_TOK; gs[i] = 0.f; }
    if (i < FIX_MAX) fixlist[i] = T_TOK;
    if (i < FIX_MAX * E_NUM) fixlogit[i] = 0.f;
    if (i == 0) *fixcount = 0;
}

// ---------------- B packing: [E][K][N] fp32 -> paired-kh fragment layout ----------
// prow p (0..Kd/4): octet o=p>>2, r=p&3 -> kh0=8o+r, kh1=kh0+4.
// out[p][n][0] = half2(B[2kh0][n],B[2kh0+1][n]); out[p][n][1] = same for kh1.
__global__ void packb_kernel(const float* __restrict__ in,
                             uint32_t* __restrict__ out, int Kd, int Nd) {
    int i = blockIdx.x * blockDim.x + threadIdx.x;
    int total = (Kd / 4) * (Nd / 4);
    if (i >= total) return;
    int p  = i / (Nd / 4);
    int nq = (i % (Nd / 4)) * 4;
    int o = p >> 2, r = p & 3;
    int k0a = 16 * o + 2 * r;         // first k of kh0
    int k0b = k0a + 8;                // first k of kh1
    const float* base = in + (size_t)blockIdx.y * Kd * Nd;
    float4 a0 = *(const float4*)(base + (size_t)(k0a    ) * Nd + nq);
    float4 a1 = *(const float4*)(base + (size_t)(k0a + 1) * Nd + nq);
    float4 b0 = *(const float4*)(base + (size_t)(k0b    ) * Nd + nq);
    float4 b1 = *(const float4*)(base + (size_t)(k0b + 1) * Nd + nq);
    uint32_t* ob = out + (size_t)blockIdx.y * ((size_t)(Kd / 2) * Nd)
                       + (size_t)p * Nd * 2 + (size_t)nq * 2;
    uint4 t0, t1;
    t0.x = pack_h2(a0.x, a1.x); t0.y = pack_h2(b0.x, b1.x);
    t0.z = pack_h2(a0.y, a1.y); t0.w = pack_h2(b0.y, b1.y);
    t1.x = pack_h2(a0.z, a1.z); t1.y = pack_h2(b0.z, b1.z);
    t1.z = pack_h2(a0.w, a1.w); t1.w = pack_h2(b0.w, b1.w);
    *(uint4*)(ob)     = t0;
    *(uint4*)(ob + 4) = t1;
}

// ---------------- FP16 tensor-core GEMM: 128x128 tile, 256 thr ----------------
// 2-stage cp.async, 2 barriers per step, BK=64, 2 CTAs/SM; ldmatrix A, LDS.64 B.
// A fp16 row-major [M][K]; B in paired-kh layout [K/4][N][2] words.
// GATHER:  A row m is A[idx[m]] (idx==T_TOK -> zero row)
// SCATTER: output row m goes to Cout[idx[m]]*gate[m] (fp32); idx==T_TOK skipped
// OUTH:    write output as fp16
template<bool GATHER, bool RELU, bool SCATTER, bool OUTH>
__global__ void __launch_bounds__(256, 2)
h16gemm_kernel(const __half* __restrict__ A, const uint32_t* __restrict__ Bp,
               const float* __restrict__ bias, void* __restrict__ CoutV,
               int N, int K,
               const int* __restrict__ rowidx, const float* __restrict__ gates,
               size_t sA, size_t sB, size_t sBias, size_t sC)
{
    constexpr int BM = 128, BN = 128, BK = 64;
    constexpr int KH = BK / 2;                    // 32 k-pairs (words per A row)
    constexpr int AS_STRIDE = KH + 4;             // 36 words/row
    constexpr int BS_STRIDE = 2 * BN + 8;         // 264 words per prow
    constexpr int AS_BUF = BM * AS_STRIDE;        // 4608 words
    constexpr int BS_BUF = 16 * BS_STRIDE;        // 4224 words (16 prows/step)
    constexpr int STAGE_WORDS = AS_BUF + BS_BUF;  // 8832 words per stage

    extern __shared__ uint32_t dsm[];             // 2 stages
    __shared__ int sRow[BM];

    const int e = blockIdx.z;
    const __half*   Ae = A    + (size_t)e * sA;
    const uint32_t* Be = Bp   + (size_t)e * sB;
    const float*    be = bias + (size_t)e * sBias;
    const int*   idxe = (GATHER || SCATTER) ? rowidx + e * CAP : nullptr;
    const float* gte  = SCATTER ? gates + e * CAP : nullptr;

    const int bm0 = blockIdx.y * BM;
    const int bn0 = blockIdx.x * BN;
    const int tid = threadIdx.x;
    const int warp = tid >> 5;
    const int lane = tid & 31;
    const int wr = warp >> 2;      // 0..1  (64-row slabs)
    const int wc = warp & 3;       // 0..3  (32-col slabs)
    const int lr = lane >> 2;      // 0..7
    const int lc = lane & 3;       // 0..3
    const int lm_row = lane & 15;            // ldmatrix row within 16-row tile
    const int lm_col = (lane >> 4) << 2;     // ldmatrix word col: 0 or 4

    if (tid < BM) {
        sRow[tid] = (GATHER || SCATTER) ? idxe[bm0 + tid] : (bm0 + tid);
    }
    __syncthreads();

    auto cpfill = [&](int s, int step) {
        const int k0 = step * BK;
        uint32_t* Asb = dsm + s * STAGE_WORDS;
        uint32_t* Bsb = Asb + AS_BUF;
        // A tile: 128 rows x 32 words = 1024 uint4 -> 4 per thread
#pragma unroll
        for (int l = 0; l < 4; l++) {
            int i2  = tid + l * 256;
            int row = i2 >> 3;                // 0..127
            int kq  = (i2 & 7) * 4;           // 0,4,...,28
            uint32_t dst = smem_u32(&Asb[row * AS_STRIDE + kq]);
            if (GATHER) {
                int src = sRow[row];
                bool ok = src < T_TOK;
                cp16(dst, Ae + (size_t)(ok ? src : 0) * K + k0 + kq * 2, ok ? 16 : 0);
            } else {
                cp16(dst, Ae + (size_t)(bm0 + row) * K + k0 + kq * 2, 16);
            }
        }
        // B tile: 16 prows x 256 words = 1024 uint4 -> 4 per thread
#pragma unroll
        for (int l = 0; l < 4; l++) {
            int i2  = tid + l * 256;
            int row = i2 >> 6;                // 0..15
            int c4  = (i2 & 63) * 4;          // 0..252
            cp16(smem_u32(&Bsb[row * BS_STRIDE + c4]),
                 Be + (size_t)(step * 16 + row) * (2 * N) + 2 * bn0 + c4, 16);
        }
        cp_commit();
    };

    float acc[4][4][4];
#pragma unroll
    for (int mt = 0; mt < 4; mt++)
#pragma unroll
        for (int nt = 0; nt < 4; nt++)
#pragma unroll
            for (int i = 0; i < 4; i++) acc[mt][nt][i] = 0.f;

    const int KS = K / BK;
    cpfill(0, 0);

    for (int step = 0; step < KS; step++) {
        const int s = step & 1;
        if (step + 1 < KS) { cpfill(s ^ 1, step + 1); cp_wait<1>(); }
        else               { cp_wait<0>(); }
        __syncthreads();                      // stage 'step' visible

        const uint32_t* As = dsm + s * STAGE_WORDS;
        const uint32_t* Bs = As + AS_BUF;

#pragma unroll
        for (int kk = 0; kk < 4; kk++) {      // four k16 steps
            const int kb = kk * 8;
            uint32_t a[4][4];
            uint2 b[4];
#pragma unroll
            for (int mt = 0; mt < 4; mt++) {
                int m0 = wr * 64 + mt * 16;
                uint32_t addr = smem_u32(&As[(m0 + lm_row) * AS_STRIDE + kb + lm_col]);
                asm volatile(
                    "ldmatrix.sync.aligned.m8n8.x4.shared.b16 {%0,%1,%2,%3}, [%4];"
                    : "=r"(a[mt][0]), "=r"(a[mt][1]),
                      "=r"(a[mt][2]), "=r"(a[mt][3])
                    : "r"(addr));
            }
#pragma unroll
            for (int nt = 0; nt < 4; nt++) {
                int n0 = wc * 32 + nt * 8;
                b[nt] = *(const uint2*)&Bs[(kk * 4 + lc) * BS_STRIDE + (n0 + lr) * 2];
            }
#pragma unroll
            for (int mt = 0; mt < 4; mt++)
#pragma unroll
                for (int nt = 0; nt < 4; nt++)
                    mma_f16(acc[mt][nt], a[mt], b[nt].x, b[nt].y);
        }
        __syncthreads();                      // reads done before buf refilled
    }

    // ---- epilogue ----
#pragma unroll
    for (int nt = 0; nt < 4; nt++) {
        int cb = wc * 32 + nt * 8 + 2 * lc;
        float bv0 = be[bn0 + cb];
        float bv1 = be[bn0 + cb + 1];
#pragma unroll
        for (int mt = 0; mt < 4; mt++) {
#pragma unroll
            for (int h = 0; h < 2; h++) {
                int lm = wr * 64 + mt * 16 + lr + h * 8;
                float v0 = acc[mt][nt][h * 2 + 0] + bv0;
                float v1 = acc[mt][nt][h * 2 + 1] + bv1;
                if (RELU) { v0 = fmaxf(v0, 0.f); v1 = fmaxf(v1, 0.f); }
                if (SCATTER) {
                    int token = sRow[lm];
                    if (token >= T_TOK) continue;
                    float g = gte[bm0 + lm];
                    v0 *= g; v1 *= g;
                    float* dst = (float*)CoutV + (size_t)token * N + bn0 + cb;
                    *(float2*)dst = make_float2(v0, v1);
                } else if (OUTH) {
                    __half* dst = (__half*)CoutV + (size_t)e * sC
                                  + (size_t)(bm0 + lm) * N + bn0 + cb;
                    *(uint32_t*)dst = pack_h2(v0, v1);
                } else {
                    float* dst = (float*)CoutV + (size_t)e * sC
                                 + (size_t)(bm0 + lm) * N + bn0 + cb;
                    *(float2*)dst = make_float2(v0, v1);
                }
            }
        }
    }
}

#define GEMM_SMEM (2 * (128 * 36 + 16 * 264) * 4)   // 70656 bytes

// ---------------- router logits (fp16 r) + gate + ambiguity flagging ----------------
__global__ void router_logits_kernel(const __half* __restrict__ r,
                                     const float* __restrict__ wr2,
                                     const float* __restrict__ br2,
                                     int* __restrict__ eid,
                                     float* __restrict__ gate,
                                     int* __restrict__ fixlist,
                                     int* __restrict__ fixcount)
{
    int warp = threadIdx.x >> 5;
    int lane = threadIdx.x & 31;
    int t = blockIdx.x * (blockDim.x >> 5) + warp;
    if (t >= T_TOK) return;

    float acc[E_NUM];
#pragma unroll
    for (int e = 0; e < E_NUM; e++) acc[e] = 0.f;

    const __half2* row = (const __half2*)(r + (size_t)t * D_DIM);
    for (int k2 = lane; k2 < D_DIM / 2; k2 += 32) {
        float2 rv = __half22float2(row[k2]);
        const float* w0 = wr2 + (size_t)(2 * k2) * E_NUM;
        const float* w1 = w0 + E_NUM;
#pragma unroll
        for (int e = 0; e < E_NUM; e++) {
            acc[e] = fmaf(rv.x, w0[e], acc[e]);
            acc[e] = fmaf(rv.y, w1[e], acc[e]);
        }
    }
#pragma unroll
    for (int e = 0; e < E_NUM; e++) {
#pragma unroll
        for (int off = 16; off > 0; off >>= 1)
            acc[e] += __shfl_xor_sync(0xFFFFFFFFu, acc[e], off);
    }
    if (lane == 0) {
        float l[E_NUM];
        float m1 = -1e30f, m2 = -1e30f;
        int best = 0;
#pragma unroll
        for (int e = 0; e < E_NUM; e++) {
            l[e] = acc[e] + br2[e];
            if (l[e] > m1) { m2 = m1; m1 = l[e]; best = e; }
            else if (l[e] > m2) m2 = l[e];
        }
        float s = 0.f;
#pragma unroll
        for (int e = 0; e < E_NUM; e++) s += __expf(l[e] - m1);
        eid[t]  = best;
        gate[t] = 1.f / s;
        if (m1 - m2 < GAP_THR) {
            int slot = atomicAdd(fixcount, 1);
            if (slot < FIX_MAX) fixlist[slot] = t;
        }
    }
}

// ---------------- exact fp32 fixup GEMM (BM=32) -> partial logits ----------------
__global__ void __launch_bounds__(256)
fix_gemm_kernel(const float* __restrict__ A, const float* __restrict__ Bmat,
                const float* __restrict__ bias, const float* __restrict__ wr2,
                const int* __restrict__ list, float* __restrict__ fixlogit,
                int N, int K)
{
    constexpr int BM = 32, BN = 128, BK = 16;
    const int bm0 = blockIdx.y * BM;
    const int bn0 = blockIdx.x * BN;
    const int tid = threadIdx.x;
    const int tx = tid & 31;
    const int ty = tid >> 5;

    if (list[bm0] >= T_TOK) return;   // whole block is padding

    __shared__ float As[BK][BM];
    __shared__ float Bs[BK][BN];
    __shared__ int   sRow[BM];
    if (tid < BM) sRow[tid] = list[bm0 + tid];
    __syncthreads();

    float acc[4][4];
#pragma unroll
    for (int i = 0; i < 4; i++)
#pragma unroll
        for (int j = 0; j < 4; j++) acc[i][j] = 0.f;

    for (int k0 = 0; k0 < K; k0 += BK) {
        if (tid < 128) {
            int row = tid >> 2;
            int c4  = (tid & 3) * 4;
            int src = sRow[row];
            float4 v = (src < T_TOK)
                ? *(const float4*)(A + (size_t)src * K + k0 + c4)
                : make_float4(0.f, 0.f, 0.f, 0.f);
            As[c4 + 0][row] = v.x;
            As[c4 + 1][row] = v.y;
            As[c4 + 2][row] = v.z;
            As[c4 + 3][row] = v.w;
        }
#pragma unroll
        for (int l = 0; l < 2; l++) {
            int i4  = tid + l * 256;
            int row = i4 >> 5;
            int c4  = (i4 & 31) * 4;
            *(float4*)(&Bs[row][c4]) =
                *(const float4*)(Bmat + (size_t)(k0 + row) * N + bn0 + c4);
        }
        __syncthreads();
#pragma unroll
        for (int kk = 0; kk < BK; kk++) {
            float a[4], b[4];
            *(float4*)(a) = *(const float4*)(&As[kk][ty * 4]);
            *(float4*)(b) = *(const float4*)(&Bs[kk][tx * 4]);
#pragma unroll
            for (int i = 0; i < 4; i++)
#pragma unroll
                for (int j = 0; j < 4; j++)
                    acc[i][j] = fmaf(a[i], b[j], acc[i][j]);
        }
        __syncthreads();
    }

    float bv[4];
#pragma unroll
    for (int j = 0; j < 4; j++) bv[j] = bias[bn0 + tx * 4 + j];

    float w2r[4][8];
#pragma unroll
    for (int j = 0; j < 4; j++) {
        const float* wrow = wr2 + (size_t)(bn0 + tx * 4 + j) * E_NUM;
        *(float4*)(&w2r[j][0]) = *(const float4*)(wrow);
        *(float4*)(&w2r[j][4]) = *(const float4*)(wrow + 4);
    }

#pragma unroll
    for (int i = 0; i < 4; i++) {
        int lrow = ty * 4 + i;
        if (sRow[lrow] >= T_TOK) continue;
        int slot = bm0 + lrow;
        float o[4];
#pragma unroll
        for (int j = 0; j < 4; j++) o[j] = fmaxf(acc[i][j] + bv[j], 0.f);
        float pl[E_NUM];
#pragma unroll
        for (int e = 0; e < E_NUM; e++) pl[e] = 0.f;
#pragma unroll
        for (int j = 0; j < 4; j++)
#pragma unroll
            for (int e = 0; e < E_NUM; e++)
                pl[e] = fmaf(o[j], w2r[j][e], pl[e]);
#pragma unroll
        for (int e = 0; e < E_NUM; e++)
            atomicAdd(&fixlogit[slot * E_NUM + e], pl[e]);
    }
}

// ---------------- capacity routing (ballot scan, applies fixups first) ----------------
__global__ void route_scan_kernel(const float* __restrict__ fixlogit,
                                  const int* __restrict__ fixlist,
                                  const float* __restrict__ br2,
                                  int* __restrict__ eid,
                                  float* __restrict__ gate,
                                  int* __restrict__ idx,
                                  float* __restrict__ gateslot)
{
    const int e = blockIdx.x;
    const int tid = threadIdx.x;
    const int lane = tid & 31;
    const int w = tid >> 5;

    for (int s = tid; s < FIX_MAX; s += 256) {
        int t = fixlist[s];
        if (t >= T_TOK) continue;
        float l[E_NUM];
        float m1 = -1e30f;
        int best = 0;
#pragma unroll
        for (int q = 0; q < E_NUM; q++) {
            l[q] = fixlogit[s * E_NUM + q] + br2[q];
            if (l[q] > m1) { m1 = l[q]; best = q; }
        }
        float sum = 0.f;
#pragma unroll
        for (int q = 0; q < E_NUM; q++) sum += __expf(l[q] - m1);
        eid[t]  = best;
        gate[t] = 1.f / sum;
    }
    __syncthreads();

    __shared__ int wsum[8];
    int base = 0;
    for (int start = 0; start < T_TOK; start += 256) {
        int t = start + tid;
        bool m = (eid[t] == e);
        unsigned bal = __ballot_sync(0xFFFFFFFFu, m);
        if (lane == 0) wsum[w] = __popc(bal);
        __syncthreads();
        int prefix = 0, total = 0;
#pragma unroll
        for (int q = 0; q < 8; q++) {
            int v = wsum[q];
            if (q < w) prefix += v;
            total += v;
        }
        if (m) {
            int p = base + prefix + __popc(bal & ((1u << lane) - 1u));
            if (p < CAP) {
                idx[e * CAP + p]      = t;
                gateslot[e * CAP + p] = gate[t];
            }
        }
        base += total;
        __syncthreads();
    }
}

// ---------------- launch ----------------
extern "C" void kernel_launch(void* const* d_in, const int* in_sizes, int n_in,
                              void* d_out, int out_size)
{
    const float* x   = (const float*)d_in[0];
    const float* wr1 = (const float*)d_in[1];
    const float* br1 = (const float*)d_in[2];
    const float* wr2 = (const float*)d_in[3];
    const float* br2 = (const float*)d_in[4];
    const float* w1  = (const float*)d_in[5];
    const float* b1  = (const float*)d_in[6];
    const float* w2  = (const float*)d_in[7];
    const float* b2  = (const float*)d_in[8];
    float* out = (float*)d_out;

    __half *xh_ptr, *h_ptr, *r_ptr;
    uint32_t *wr1p_ptr, *w1p_ptr, *w2p_ptr;
    float *gate_ptr, *gs_ptr, *fixlogit_ptr;
    int *eid_ptr, *idx_ptr, *fixlist_ptr, *fixcount_ptr;
    cudaGetSymbolAddress((void**)&xh_ptr,       g_xh);
    cudaGetSymbolAddress((void**)&wr1p_ptr,     g_wr1p);
    cudaGetSymbolAddress((void**)&w1p_ptr,      g_w1p);
    cudaGetSymbolAddress((void**)&w2p_ptr,      g_w2p);
    cudaGetSymbolAddress((void**)&r_ptr,        g_r);
    cudaGetSymbolAddress((void**)&h_ptr,        g_h);
    cudaGetSymbolAddress((void**)&fixlogit_ptr, g_fixlogit);
    cudaGetSymbolAddress((void**)&fixlist_ptr,  g_fixlist);
    cudaGetSymbolAddress((void**)&fixcount_ptr, g_fixcount);
    cudaGetSymbolAddress((void**)&gate_ptr,     g_gate);
    cudaGetSymbolAddress((void**)&gs_ptr,       g_gateslot);
    cudaGetSymbolAddress((void**)&eid_ptr,      g_eid);
    cudaGetSymbolAddress((void**)&idx_ptr,      g_idx);

    cudaFuncSetAttribute(h16gemm_kernel<false, true, false, true>,
                         cudaFuncAttributeMaxDynamicSharedMemorySize, GEMM_SMEM);
    cudaFuncSetAttribute(h16gemm_kernel<true, true, false, true>,
                         cudaFuncAttributeMaxDynamicSharedMemorySize, GEMM_SMEM);
    cudaFuncSetAttribute(h16gemm_kernel<false, false, true, false>,
                         cudaFuncAttributeMaxDynamicSharedMemorySize, GEMM_SMEM);

    // 1) fused prep: zero out, init routing state, x -> fp16
    {
        int n4 = ((size_t)T_TOK * D_DIM) / 4;
        prep_kernel<<<(n4 + 255) / 256, 256>>>(
            (float4*)out, n4, idx_ptr, gs_ptr, fixlist_ptr, fixcount_ptr,
            fixlogit_ptr, (const float4*)x, (uint2*)xh_ptr);
    }

    // 2) weight packing (paired-kh layout): wr1, w1
    {
        int nb = (D_DIM / 4) * (D_DIM / 4);
        packb_kernel<<<dim3((nb + 255) / 256, 1), 256>>>(wr1, wr1p_ptr, D_DIM, D_DIM);
        nb = (D_DIM / 4) * (H_DIM / 4);
        packb_kernel<<<dim3((nb + 255) / 256, E_NUM), 256>>>(w1, w1p_ptr, D_DIM, H_DIM);
    }

    // 3) r = relu(x @ wr1 + br1)   -- fp16 tensor cores, fp16 out
    {
        dim3 grid(D_DIM / 128, T_TOK / 128, 1);
        h16gemm_kernel<false, true, false, true><<<grid, 256, GEMM_SMEM>>>(
            xh_ptr, wr1p_ptr, br1, r_ptr, D_DIM, D_DIM,
            nullptr, nullptr, 0, 0, 0, (size_t)0);
    }

    // 4) logits -> eid, gate, flag ambiguous tokens
    router_logits_kernel<<<T_TOK / 8, 256>>>(r_ptr, wr2, br2, eid_ptr, gate_ptr,
                                             fixlist_ptr, fixcount_ptr);

    // 5) exact fp32 partial logits for flagged tokens
    {
        dim3 grid(D_DIM / 128, FIX_MAX / 32, 1);
        fix_gemm_kernel<<<grid, 256>>>(x, wr1, br1, wr2, fixlist_ptr,
                                       fixlogit_ptr, D_DIM, D_DIM);
    }

    // 6) apply fixups + routing scan
    route_scan_kernel<<<E_NUM, 256>>>(fixlogit_ptr, fixlist_ptr, br2,
                                      eid_ptr, gate_ptr, idx_ptr, gs_ptr);

    // 7) h[e] = relu(gather(xh, idx[e]) @ w1[e] + b1[e])  -> fp16 hidden
    {
        dim3 grid(H_DIM / 128, CAP / 128, E_NUM);
        h16gemm_kernel<true, true, false, true><<<grid, 256, GEMM_SMEM>>>(
            xh_ptr, w1p_ptr, b1, h_ptr, H_DIM, D_DIM,
            idx_ptr, nullptr,
            0, (size_t)(D_DIM / 2) * H_DIM, H_DIM, (size_t)CAP * H_DIM);
    }

    // 7b) pack w2 (paired-kh layout)
    {
        int nb = (H_DIM / 4) * (D_DIM / 4);
        packb_kernel<<<dim3((nb + 255) / 256, E_NUM), 256>>>(w2, w2p_ptr, H_DIM, D_DIM);
    }

    // 8) out[idx] = gate * (h[e] @ w2[e] + b2[e])
    {
        dim3 grid(D_DIM / 128, CAP / 128, E_NUM);
        h16gemm_kernel<false, false, true, false><<<grid, 256, GEMM_SMEM>>>(
            h_ptr, w2p_ptr, b2, out, D_DIM, H_DIM,
            idx_ptr, gs_ptr,
            (size_t)CAP * H_DIM, (size_t)(H_DIM / 2) * D_DIM, D_DIM, 0);
    }
}